// round 9
// baseline (speedup 1.0000x reference)
#include <cuda_runtime.h>
#include <math.h>
#include <stdint.h>

// MultiHeadAttention B=8 S=1024 HIDDEN=1024 HEADS=16 HEAD_DIM=64
// mma.sync tf32 path (tcgen05 unavailable: harness PTX target is sm_103, not sm_103a)
#define BATCH 8
#define SEQ 1024
#define HIDDEN 1024
#define HEADS 16
#define HEAD_DIM 64
#define MTOT (BATCH * SEQ)          // 8192
#define QKV_N (3 * HIDDEN)          // 3072

// scratch (__device__ globals: allocation-free rule)
__device__ float g_qkv[MTOT * QKV_N];     // 96 MB (tf32-rounded by GEMM1 epilogue)
__device__ float g_att[MTOT * HIDDEN];    // 32 MB (tf32-rounded)
__device__ float g_x  [MTOT * HIDDEN];    // tf32-rounded X
__device__ float g_w1t[QKV_N * HIDDEN];   // Wqkv^T [N,K], tf32-rounded
__device__ float g_w2t[HIDDEN * HIDDEN];  // Wo^T   [N,K], tf32-rounded

// ---------------------------------------------------------------------------
__device__ __forceinline__ uint32_t f2tf(float f) {
    uint32_t u; asm("cvt.rna.tf32.f32 %0, %1;" : "=r"(u) : "f"(f)); return u;
}
__device__ __forceinline__ uint32_t fbits(float f) { return __float_as_uint(f); }

__device__ __forceinline__ void mma8(float* c, uint32_t a0, uint32_t a1, uint32_t a2, uint32_t a3,
                                     uint32_t b0, uint32_t b1) {
    asm volatile(
        "mma.sync.aligned.m16n8k8.row.col.f32.tf32.tf32.f32 "
        "{%0,%1,%2,%3},{%4,%5,%6,%7},{%8,%9},{%0,%1,%2,%3};"
        : "+f"(c[0]), "+f"(c[1]), "+f"(c[2]), "+f"(c[3])
        : "r"(a0), "r"(a1), "r"(a2), "r"(a3), "r"(b0), "r"(b1));
}

__device__ __forceinline__ void ldsm4(uint32_t* d, uint32_t a) {
    asm volatile("ldmatrix.sync.aligned.m8n8.x4.shared.b16 {%0,%1,%2,%3}, [%4];"
                 : "=r"(d[0]), "=r"(d[1]), "=r"(d[2]), "=r"(d[3]) : "r"(a));
}

__device__ __forceinline__ void cp16(uint32_t dst, const void* src) {
    asm volatile("cp.async.cg.shared.global [%0], [%1], 16;" :: "r"(dst), "l"(src));
}
__device__ __forceinline__ void cp_commit() { asm volatile("cp.async.commit_group;"); }
template <int n> __device__ __forceinline__ void cp_wait() {
    asm volatile("cp.async.wait_group %0;" :: "n"(n));
}
__device__ __forceinline__ uint32_t smem_u32(const void* p) {
    return (uint32_t)__cvta_generic_to_shared(p);
}

// ---------------------------------------------------------------------------
// prep kernels
// ---------------------------------------------------------------------------
__global__ void k_round(const float* __restrict__ in, float* __restrict__ out, int n4) {
    int i = blockIdx.x * blockDim.x + threadIdx.x;
    if (i < n4) {
        float4 v = ((const float4*)in)[i];
        v.x = __uint_as_float(f2tf(v.x));
        v.y = __uint_as_float(f2tf(v.y));
        v.z = __uint_as_float(f2tf(v.z));
        v.w = __uint_as_float(f2tf(v.w));
        ((float4*)out)[i] = v;
    }
}

// in[R][C] -> out[C][R], tf32-rounded.  block (32,8), grid (C/32, R/32)
__global__ void k_transpose_tf(const float* __restrict__ in, float* __restrict__ out, int R, int C) {
    __shared__ float t[32][33];
    int c = blockIdx.x * 32 + threadIdx.x;
    int r0 = blockIdx.y * 32 + threadIdx.y;
#pragma unroll
    for (int i = 0; i < 32; i += 8)
        t[threadIdx.y + i][threadIdx.x] = in[(size_t)(r0 + i) * C + c];
    __syncthreads();
    int rr = blockIdx.y * 32 + threadIdx.x;
    int cc0 = blockIdx.x * 32 + threadIdx.y;
#pragma unroll
    for (int i = 0; i < 32; i += 8)
        out[(size_t)(cc0 + i) * R + rr] = __uint_as_float(f2tf(t[threadIdx.x][threadIdx.y + i]));
}

// ---------------------------------------------------------------------------
// tf32 GEMM via mma.sync + ldmatrix: C[M,NTOT] = A[M,1024] @ Bt[N,1024]^T + bias
// CTA tile 128x256, 8 warps, warp tile 64x64 (max fragment reuse:
// 4 KB fragments -> 32 MMAs per ks vs 6 KB -> 16 before; crossbar-bound fix).
// BK=16, 4-stage cp.async ring, one __syncthreads per k-tile.
// smem rows: 16 floats + 4 pad (80B) — conflict-free ldmatrix phases.
// Stage: A 128 rows (10240 B) + B 256 rows (20480 B) = 30720 B; 4 stages.
// ROUND: tf32-round output (GEMM1 -> feeds attention unconverted).
// ---------------------------------------------------------------------------
#define GSTG_BYTES 30720
#define GEMM_SMEM (4 * GSTG_BYTES)    // 122880

template <int NTOT, bool ROUND>
__global__ void __launch_bounds__(256, 1) gemm_tc(const float* __restrict__ A,
                                                  const float* __restrict__ Bt,
                                                  const float* __restrict__ bias,
                                                  float* __restrict__ C) {
    extern __shared__ char smem[];
    const uint32_t sb = smem_u32(smem);
    const int tid = threadIdx.x;
    const int lane = tid & 31;
    const int warp = tid >> 5;
    const int bm = blockIdx.y * 128;
    const int bn = blockIdx.x * 256;
    const int wm = (warp & 1) * 64;        // 0,64
    const int wn = (warp >> 1) * 64;       // 0,64,128,192
    const int r  = lane >> 2;
    const int cc = lane & 3;
    const int K = HIDDEN;

    // staging: A row = tid>>1 (2 cp16), B row = tid (4 cp16)
    const float* Ag = A  + (size_t)(bm + (tid >> 1)) * K + (tid & 1) * 8;
    const float* Bg = Bt + (size_t)(bn + tid) * K;
    const uint32_t sA = sb + (uint32_t)(tid >> 1) * 80 + (uint32_t)(tid & 1) * 32;
    const uint32_t sB = sb + 10240 + (uint32_t)tid * 80;

    auto load = [&](int kb) {
        const uint32_t o = (uint32_t)(kb & 3) * GSTG_BYTES;
        const float* a = Ag + kb * 16;
        const float* b2 = Bg + kb * 16;
        cp16(sA + o,      a);
        cp16(sA + o + 16, a + 4);
#pragma unroll
        for (int i = 0; i < 4; i++) cp16(sB + o + i * 16, b2 + i * 4);
    };

    float acc[4][8][4];
#pragma unroll
    for (int i = 0; i < 4; i++)
#pragma unroll
        for (int j = 0; j < 8; j++)
#pragma unroll
            for (int q = 0; q < 4; q++) acc[i][j][q] = 0.f;

    // ldmatrix lane address offsets (bytes): 16 rows x {0,16B}
    const uint32_t aLane = (uint32_t)(wm + (lane & 15)) * 80 + (uint32_t)(lane & 16);
    const uint32_t bLane = 10240 + (uint32_t)(wn + (lane & 15)) * 80 + (uint32_t)(lane & 16);

    load(0); cp_commit();
    load(1); cp_commit();
    load(2); cp_commit();

    const int NT = K / 16;   // 64
    for (int kb = 0; kb < NT; kb++) {
        cp_wait<2>();
        __syncthreads();
        if (kb + 3 < NT) load(kb + 3);
        cp_commit();

        const uint32_t st = sb + (uint32_t)(kb & 3) * GSTG_BYTES;
        const uint32_t Ab = st + aLane;
        const uint32_t Bb = st + bLane;
#pragma unroll
        for (int ks = 0; ks < 2; ks++) {
            uint32_t af[4][4], bq[4][4];
#pragma unroll
            for (int i = 0; i < 4; i++)  ldsm4(af[i],  Ab + i * 1280 + ks * 32);
#pragma unroll
            for (int j2 = 0; j2 < 4; j2++) ldsm4(bq[j2], Bb + j2 * 1280 + ks * 32);
#pragma unroll
            for (int i = 0; i < 4; i++)
#pragma unroll
                for (int j2 = 0; j2 < 4; j2++) {
                    mma8(acc[i][2 * j2],     af[i][0], af[i][1], af[i][2], af[i][3],
                         bq[j2][0], bq[j2][2]);
                    mma8(acc[i][2 * j2 + 1], af[i][0], af[i][1], af[i][2], af[i][3],
                         bq[j2][1], bq[j2][3]);
                }
        }
    }

    // epilogue: bias (+ optional tf32 round) + store
#pragma unroll
    for (int i = 0; i < 4; i++) {
        const int row0 = bm + wm + 16 * i + r;
#pragma unroll
        for (int j = 0; j < 8; j++) {
            const int col = bn + wn + 8 * j + 2 * cc;
            const float b0 = bias[col], b1 = bias[col + 1];
            float v00 = acc[i][j][0] + b0, v01 = acc[i][j][1] + b1;
            float v10 = acc[i][j][2] + b0, v11 = acc[i][j][3] + b1;
            if (ROUND) {
                v00 = __uint_as_float(f2tf(v00));
                v01 = __uint_as_float(f2tf(v01));
                v10 = __uint_as_float(f2tf(v10));
                v11 = __uint_as_float(f2tf(v11));
            }
            *(float2*)&C[(size_t)row0 * NTOT + col]       = make_float2(v00, v01);
            *(float2*)&C[(size_t)(row0 + 8) * NTOT + col] = make_float2(v10, v11);
        }
    }
}

// ---------------------------------------------------------------------------
// Flash attention, tf32 mma.sync (unchanged from R8).
// ---------------------------------------------------------------------------
#define KROW 68
#define VROW 72
#define KBUF (64 * KROW)
#define VBUF (64 * VROW)
#define ATT_SMEM ((2 * KBUF + 2 * VBUF) * 4)   // 71680

__global__ void __launch_bounds__(256, 2) k_attention() {
    extern __shared__ float sm[];
    float* Kb = sm;
    float* Vb = sm + 2 * KBUF;

    const int tid  = threadIdx.x;
    const int lane = tid & 31;
    const int warp = tid >> 5;
    const int qt = blockIdx.x;
    const int h  = blockIdx.y;
    const int b  = blockIdx.z;
    const int r  = lane >> 2;
    const int c  = lane & 3;

    uint32_t qf[8][4];
    {
        const float* Qp = g_qkv + (size_t)(b * SEQ + qt * 128 + warp * 16) * QKV_N + h * HEAD_DIM;
#pragma unroll
        for (int ks = 0; ks < 8; ks++) {
            qf[ks][0] = fbits(Qp[(size_t)r       * QKV_N + 8 * ks + c    ] * 0.125f);
            qf[ks][1] = fbits(Qp[(size_t)(r + 8) * QKV_N + 8 * ks + c    ] * 0.125f);
            qf[ks][2] = fbits(Qp[(size_t)r       * QKV_N + 8 * ks + c + 4] * 0.125f);
            qf[ks][3] = fbits(Qp[(size_t)(r + 8) * QKV_N + 8 * ks + c + 4] * 0.125f);
        }
    }

    const int srow = tid >> 2;
    const int sc0  = (tid & 3) * 16;
    const float* kbase = g_qkv + (size_t)(b * SEQ) * QKV_N + HIDDEN + h * HEAD_DIM + sc0;

    auto load_chunk = [&](int ct, int buf) {
        const float* kp = kbase + (size_t)(ct * 64 + srow) * QKV_N;
        const float* vp = kp + HIDDEN;
        const uint32_t kd = smem_u32(&Kb[buf * KBUF + srow * KROW + sc0]);
        const uint32_t vd = smem_u32(&Vb[buf * VBUF + srow * VROW + sc0]);
#pragma unroll
        for (int i = 0; i < 4; i++) cp16(kd + i * 16, kp + i * 4);
#pragma unroll
        for (int i = 0; i < 4; i++) cp16(vd + i * 16, vp + i * 4);
    };

    float m0 = -INFINITY, m1 = -INFINITY, l0 = 0.f, l1 = 0.f;
    float o[8][4];
#pragma unroll
    for (int j = 0; j < 8; j++)
#pragma unroll
        for (int q = 0; q < 4; q++) o[j][q] = 0.f;

    load_chunk(0, 0);
    cp_commit();

    for (int ct = 0; ct < 16; ct++) {
        const int buf = ct & 1;
        cp_wait<0>();
        __syncthreads();
        if (ct + 1 < 16) load_chunk(ct + 1, buf ^ 1);
        cp_commit();

        const float* Ks = &Kb[buf * KBUF];
        const float* Vs = &Vb[buf * VBUF];

        float s[8][4];
#pragma unroll
        for (int j = 0; j < 8; j++)
#pragma unroll
            for (int q = 0; q < 4; q++) s[j][q] = 0.f;

#pragma unroll
        for (int j = 0; j < 8; j++)
#pragma unroll
            for (int ks = 0; ks < 8; ks++) {
                uint32_t b0 = fbits(Ks[(8 * j + r) * KROW + 8 * ks + c]);
                uint32_t b1 = fbits(Ks[(8 * j + r) * KROW + 8 * ks + c + 4]);
                mma8(s[j], qf[ks][0], qf[ks][1], qf[ks][2], qf[ks][3], b0, b1);
            }

        float mx0 = -INFINITY, mx1 = -INFINITY;
#pragma unroll
        for (int j = 0; j < 8; j++) {
            mx0 = fmaxf(mx0, fmaxf(s[j][0], s[j][1]));
            mx1 = fmaxf(mx1, fmaxf(s[j][2], s[j][3]));
        }
#pragma unroll
        for (int off = 1; off < 4; off <<= 1) {
            mx0 = fmaxf(mx0, __shfl_xor_sync(0xffffffffu, mx0, off));
            mx1 = fmaxf(mx1, __shfl_xor_sync(0xffffffffu, mx1, off));
        }
        const float nm0 = fmaxf(m0, mx0), nm1 = fmaxf(m1, mx1);
        const float cor0 = __expf(m0 - nm0), cor1 = __expf(m1 - nm1);
        m0 = nm0; m1 = nm1;
        float rs0 = 0.f, rs1 = 0.f;
#pragma unroll
        for (int j = 0; j < 8; j++) {
            s[j][0] = __expf(s[j][0] - nm0);
            s[j][1] = __expf(s[j][1] - nm0);
            s[j][2] = __expf(s[j][2] - nm1);
            s[j][3] = __expf(s[j][3] - nm1);
            rs0 += s[j][0] + s[j][1];
            rs1 += s[j][2] + s[j][3];
        }
#pragma unroll
        for (int off = 1; off < 4; off <<= 1) {
            rs0 += __shfl_xor_sync(0xffffffffu, rs0, off);
            rs1 += __shfl_xor_sync(0xffffffffu, rs1, off);
        }
        l0 = l0 * cor0 + rs0;
        l1 = l1 * cor1 + rs1;
#pragma unroll
        for (int j = 0; j < 8; j++) {
            o[j][0] *= cor0; o[j][1] *= cor0;
            o[j][2] *= cor1; o[j][3] *= cor1;
        }

        const int sbase = lane & ~3;
        const int src1 = sbase | (c >> 1);
        const int src2 = sbase | 2 | (c >> 1);
        const bool odd = (c & 1);
#pragma unroll
        for (int kt = 0; kt < 8; kt++) {
            uint32_t p0 = f2tf(s[kt][0]), p1 = f2tf(s[kt][1]);
            uint32_t p2 = f2tf(s[kt][2]), p3 = f2tf(s[kt][3]);
            uint32_t x0 = __shfl_sync(0xffffffffu, p0, src1);
            uint32_t x1 = __shfl_sync(0xffffffffu, p1, src1);
            uint32_t x2 = __shfl_sync(0xffffffffu, p2, src1);
            uint32_t x3 = __shfl_sync(0xffffffffu, p3, src1);
            uint32_t y0 = __shfl_sync(0xffffffffu, p0, src2);
            uint32_t y1 = __shfl_sync(0xffffffffu, p1, src2);
            uint32_t y2 = __shfl_sync(0xffffffffu, p2, src2);
            uint32_t y3 = __shfl_sync(0xffffffffu, p3, src2);
            uint32_t a0 = odd ? x1 : x0;
            uint32_t a1 = odd ? x3 : x2;
            uint32_t a2 = odd ? y1 : y0;
            uint32_t a3 = odd ? y3 : y2;
#pragma unroll
            for (int j = 0; j < 8; j++) {
                uint32_t b0 = fbits(Vs[(8 * kt + c    ) * VROW + 8 * j + r]);
                uint32_t b1 = fbits(Vs[(8 * kt + c + 4) * VROW + 8 * j + r]);
                mma8(o[j], a0, a1, a2, a3, b0, b1);
            }
        }
    }

    const float inv0 = 1.f / l0, inv1 = 1.f / l1;
    const size_t gq = (size_t)(b * SEQ + qt * 128 + warp * 16);
#pragma unroll
    for (int j = 0; j < 8; j++) {
        const int col = h * HEAD_DIM + 8 * j + 2 * c;
        float2 v0, v1;
        v0.x = __uint_as_float(f2tf(o[j][0] * inv0));
        v0.y = __uint_as_float(f2tf(o[j][1] * inv0));
        v1.x = __uint_as_float(f2tf(o[j][2] * inv1));
        v1.y = __uint_as_float(f2tf(o[j][3] * inv1));
        *(float2*)&g_att[(gq + r) * HIDDEN + col]     = v0;
        *(float2*)&g_att[(gq + r + 8) * HIDDEN + col] = v1;
    }
}

// ---------------------------------------------------------------------------
extern "C" void kernel_launch(void* const* d_in, const int* in_sizes, int n_in,
                              void* d_out, int out_size) {
    const float* query = (const float*)d_in[0];
    const float* w_qkv = (const float*)d_in[1];
    const float* b_qkv = (const float*)d_in[2];
    const float* w_o   = (const float*)d_in[3];
    const float* b_o   = (const float*)d_in[4];
    float* out = (float*)d_out;

    float *gx, *gw1t, *gw2t, *gqkv, *gatt;
    cudaGetSymbolAddress((void**)&gx,   g_x);
    cudaGetSymbolAddress((void**)&gw1t, g_w1t);
    cudaGetSymbolAddress((void**)&gw2t, g_w2t);
    cudaGetSymbolAddress((void**)&gqkv, g_qkv);
    cudaGetSymbolAddress((void**)&gatt, g_att);

    cudaFuncSetAttribute(gemm_tc<QKV_N, true>,   cudaFuncAttributeMaxDynamicSharedMemorySize, GEMM_SMEM);
    cudaFuncSetAttribute(gemm_tc<HIDDEN, false>, cudaFuncAttributeMaxDynamicSharedMemorySize, GEMM_SMEM);
    cudaFuncSetAttribute(k_attention,            cudaFuncAttributeMaxDynamicSharedMemorySize, ATT_SMEM);

    // prep: round X; transpose+round weights
    {
        int n4x = MTOT * HIDDEN / 4;
        k_round<<<(n4x + 255) / 256, 256>>>(query, gx, n4x);
        dim3 tb(32, 8);
        k_transpose_tf<<<dim3(QKV_N / 32, HIDDEN / 32), tb>>>(w_qkv, gw1t, HIDDEN, QKV_N);
        k_transpose_tf<<<dim3(HIDDEN / 32, HIDDEN / 32), tb>>>(w_o, gw2t, HIDDEN, HIDDEN);
    }

    // QKV GEMM (rounds output to tf32 for attention)
    gemm_tc<QKV_N, true><<<dim3(QKV_N / 256, MTOT / 128), 256, GEMM_SMEM>>>(gx, gw1t, b_qkv, gqkv);

    // flash attention
    k_attention<<<dim3(SEQ / 128, HEADS, BATCH), 256, ATT_SMEM>>>();

    // output GEMM
    gemm_tc<HIDDEN, false><<<dim3(HIDDEN / 256, MTOT / 128), 256, GEMM_SMEM>>>(gatt, gw2t, b_o, out);
}

// round 12
// speedup vs baseline: 1.2569x; 1.2569x over previous
#include <cuda_runtime.h>
#include <math.h>
#include <stdint.h>

// MultiHeadAttention B=8 S=1024 HIDDEN=1024 HEADS=16 HEAD_DIM=64
// mma.sync tf32 path (tcgen05 unavailable: harness PTX target is sm_103, not sm_103a)
#define BATCH 8
#define SEQ 1024
#define HIDDEN 1024
#define HEADS 16
#define HEAD_DIM 64
#define MTOT (BATCH * SEQ)          // 8192
#define QKV_N (3 * HIDDEN)          // 3072

// scratch (__device__ globals: allocation-free rule)
__device__ float g_qkv[MTOT * QKV_N];     // 96 MB (tf32-rounded by GEMM1 epilogue)
__device__ float g_att[MTOT * HIDDEN];    // 32 MB (tf32-rounded)
__device__ float g_x  [MTOT * HIDDEN];    // tf32-rounded X
__device__ float g_w1t[QKV_N * HIDDEN];   // Wqkv^T [N,K], tf32-rounded
__device__ float g_w2t[HIDDEN * HIDDEN];  // Wo^T   [N,K], tf32-rounded

// ---------------------------------------------------------------------------
__device__ __forceinline__ uint32_t f2tf(float f) {
    uint32_t u; asm("cvt.rna.tf32.f32 %0, %1;" : "=r"(u) : "f"(f)); return u;
}
__device__ __forceinline__ uint32_t fbits(float f) { return __float_as_uint(f); }
__device__ __forceinline__ float ex2(float x) {
    float y; asm("ex2.approx.ftz.f32 %0, %1;" : "=f"(y) : "f"(x)); return y;
}

__device__ __forceinline__ void mma8(float* c, uint32_t a0, uint32_t a1, uint32_t a2, uint32_t a3,
                                     uint32_t b0, uint32_t b1) {
    asm volatile(
        "mma.sync.aligned.m16n8k8.row.col.f32.tf32.tf32.f32 "
        "{%0,%1,%2,%3},{%4,%5,%6,%7},{%8,%9},{%0,%1,%2,%3};"
        : "+f"(c[0]), "+f"(c[1]), "+f"(c[2]), "+f"(c[3])
        : "r"(a0), "r"(a1), "r"(a2), "r"(a3), "r"(b0), "r"(b1));
}

__device__ __forceinline__ void ldsm4(uint32_t* d, uint32_t a) {
    asm volatile("ldmatrix.sync.aligned.m8n8.x4.shared.b16 {%0,%1,%2,%3}, [%4];"
                 : "=r"(d[0]), "=r"(d[1]), "=r"(d[2]), "=r"(d[3]) : "r"(a));
}
__device__ __forceinline__ void ldsm2(uint32_t* d, uint32_t a) {
    asm volatile("ldmatrix.sync.aligned.m8n8.x2.shared.b16 {%0,%1}, [%2];"
                 : "=r"(d[0]), "=r"(d[1]) : "r"(a));
}

__device__ __forceinline__ void cp16(uint32_t dst, const void* src) {
    asm volatile("cp.async.cg.shared.global [%0], [%1], 16;" :: "r"(dst), "l"(src));
}
__device__ __forceinline__ void cp_commit() { asm volatile("cp.async.commit_group;"); }
template <int n> __device__ __forceinline__ void cp_wait() {
    asm volatile("cp.async.wait_group %0;" :: "n"(n));
}
__device__ __forceinline__ uint32_t smem_u32(const void* p) {
    return (uint32_t)__cvta_generic_to_shared(p);
}

// ---------------------------------------------------------------------------
// prep kernels
// ---------------------------------------------------------------------------
__global__ void k_round(const float* __restrict__ in, float* __restrict__ out, int n4) {
    int i = blockIdx.x * blockDim.x + threadIdx.x;
    if (i < n4) {
        float4 v = ((const float4*)in)[i];
        v.x = __uint_as_float(f2tf(v.x));
        v.y = __uint_as_float(f2tf(v.y));
        v.z = __uint_as_float(f2tf(v.z));
        v.w = __uint_as_float(f2tf(v.w));
        ((float4*)out)[i] = v;
    }
}

// in[R][C] -> out[C][R], tf32-rounded.  block (32,8), grid (C/32, R/32)
__global__ void k_transpose_tf(const float* __restrict__ in, float* __restrict__ out, int R, int C) {
    __shared__ float t[32][33];
    int c = blockIdx.x * 32 + threadIdx.x;
    int r0 = blockIdx.y * 32 + threadIdx.y;
#pragma unroll
    for (int i = 0; i < 32; i += 8)
        t[threadIdx.y + i][threadIdx.x] = in[(size_t)(r0 + i) * C + c];
    __syncthreads();
    int rr = blockIdx.y * 32 + threadIdx.x;
    int cc0 = blockIdx.x * 32 + threadIdx.y;
#pragma unroll
    for (int i = 0; i < 32; i += 8)
        out[(size_t)(cc0 + i) * R + rr] = __uint_as_float(f2tf(t[threadIdx.x][threadIdx.y + i]));
}

// ---------------------------------------------------------------------------
// tf32 GEMM via mma.sync + ldmatrix (R8 config — validated 47.7% tensor):
// CTA 128x128, BK=16, 8 warps (warp tile 64x32), 4-stage cp.async ring,
// one __syncthreads per k-tile, 2 CTAs/SM (regs<=128).
// smem rows: 16 floats + 4 pad (80B). Stage = 20480 B; 4 stages = 80 KB.
// ROUND: tf32-round the output (GEMM1 -> feeds attention unconverted).
// ---------------------------------------------------------------------------
#define GSTG_BYTES 20480
#define GEMM_SMEM (4 * GSTG_BYTES)    // 81920

template <int NTOT, bool ROUND>
__global__ void __launch_bounds__(256, 2) gemm_tc(const float* __restrict__ A,
                                                  const float* __restrict__ Bt,
                                                  const float* __restrict__ bias,
                                                  float* __restrict__ C) {
    extern __shared__ char smem[];
    const uint32_t sb = smem_u32(smem);
    const int tid = threadIdx.x;
    const int lane = tid & 31;
    const int warp = tid >> 5;
    const int bm = blockIdx.y * 128;
    const int bn = blockIdx.x * 128;
    const int wm = (warp & 1) * 64;
    const int wn = (warp >> 1) * 32;
    const int r  = lane >> 2;
    const int cc = lane & 3;
    const int K = HIDDEN;

    const int srow = tid >> 1;
    const int scol = (tid & 1) * 8;
    const float* Ag = A  + (size_t)(bm + srow) * K + scol;
    const float* Bg = Bt + (size_t)(bn + srow) * K + scol;
    const uint32_t sA = sb + (uint32_t)srow * 80 + (uint32_t)scol * 4;
    const uint32_t sB = sA + 10240;

    auto load = [&](int kb) {
        const uint32_t o = (uint32_t)(kb & 3) * GSTG_BYTES;
        const float* a = Ag + kb * 16;
        const float* b2 = Bg + kb * 16;
        cp16(sA + o,      a);
        cp16(sA + o + 16, a + 4);
        cp16(sB + o,      b2);
        cp16(sB + o + 16, b2 + 4);
    };

    float acc[4][4][4];
#pragma unroll
    for (int i = 0; i < 4; i++)
#pragma unroll
        for (int j = 0; j < 4; j++)
#pragma unroll
            for (int q = 0; q < 4; q++) acc[i][j][q] = 0.f;

    const uint32_t aLane = (uint32_t)(wm + (lane & 15)) * 80 + (uint32_t)(lane & 16);
    const uint32_t bLane = 10240 + (uint32_t)(wn + (lane & 7)) * 80 + (uint32_t)((lane & 8) * 2);

    load(0); cp_commit();
    load(1); cp_commit();
    load(2); cp_commit();

    const int NT = K / 16;   // 64
    for (int kb = 0; kb < NT; kb++) {
        cp_wait<2>();
        __syncthreads();
        if (kb + 3 < NT) load(kb + 3);
        cp_commit();

        const uint32_t st = sb + (uint32_t)(kb & 3) * GSTG_BYTES;
        const uint32_t Ab = st + aLane;
        const uint32_t Bb = st + bLane;
#pragma unroll
        for (int ks = 0; ks < 2; ks++) {
            uint32_t af[4][4], bf[4][2];
#pragma unroll
            for (int i = 0; i < 4; i++) ldsm4(af[i], Ab + i * 1280 + ks * 32);
#pragma unroll
            for (int j = 0; j < 4; j++) ldsm2(bf[j], Bb + j * 640 + ks * 32);
#pragma unroll
            for (int i = 0; i < 4; i++)
#pragma unroll
                for (int j = 0; j < 4; j++)
                    mma8(acc[i][j], af[i][0], af[i][1], af[i][2], af[i][3], bf[j][0], bf[j][1]);
        }
    }

    // epilogue: bias (+ optional tf32 round) + store
#pragma unroll
    for (int i = 0; i < 4; i++) {
        const int row0 = bm + wm + 16 * i + r;
#pragma unroll
        for (int j = 0; j < 4; j++) {
            const int col = bn + wn + 8 * j + 2 * cc;
            const float b0 = bias[col], b1 = bias[col + 1];
            float v00 = acc[i][j][0] + b0, v01 = acc[i][j][1] + b1;
            float v10 = acc[i][j][2] + b0, v11 = acc[i][j][3] + b1;
            if (ROUND) {
                v00 = __uint_as_float(f2tf(v00));
                v01 = __uint_as_float(f2tf(v01));
                v10 = __uint_as_float(f2tf(v10));
                v11 = __uint_as_float(f2tf(v11));
            }
            *(float2*)&C[(size_t)row0 * NTOT + col]       = make_float2(v00, v01);
            *(float2*)&C[(size_t)(row0 + 8) * NTOT + col] = make_float2(v10, v11);
        }
    }
}

// ---------------------------------------------------------------------------
// Flash attention, tf32 mma.sync. 256 threads (8 warps), q-block 128,
// K/V streamed in 64-token chunks via cp.async double buffer.
// R10: K fragments via ldmatrix.x4 (128 LDS -> 32 LDSM per warp-iter;
// mapping verified numerically in R9's GEMM), softmax in exp2 domain
// (log2e folded into Q scale -> bare MUFU.EX2).
// ---------------------------------------------------------------------------
#define KROW 68
#define VROW 72
#define KBUF (64 * KROW)
#define VBUF (64 * VROW)
#define ATT_SMEM ((2 * KBUF + 2 * VBUF) * 4)   // 71680

__global__ void __launch_bounds__(256, 2) k_attention() {
    extern __shared__ float sm[];
    float* Kb = sm;
    float* Vb = sm + 2 * KBUF;

    const int tid  = threadIdx.x;
    const int lane = tid & 31;
    const int warp = tid >> 5;
    const int qt = blockIdx.x;
    const int h  = blockIdx.y;
    const int b  = blockIdx.z;
    const int r  = lane >> 2;
    const int c  = lane & 3;

    // ---- Q fragments: scale = 1/8 * log2(e), re-round to tf32 ----
    const float qscale = 0.125f * 1.4426950408889634f;
    uint32_t qf[8][4];
    {
        const float* Qp = g_qkv + (size_t)(b * SEQ + qt * 128 + warp * 16) * QKV_N + h * HEAD_DIM;
#pragma unroll
        for (int ks = 0; ks < 8; ks++) {
            qf[ks][0] = f2tf(Qp[(size_t)r       * QKV_N + 8 * ks + c    ] * qscale);
            qf[ks][1] = f2tf(Qp[(size_t)(r + 8) * QKV_N + 8 * ks + c    ] * qscale);
            qf[ks][2] = f2tf(Qp[(size_t)r       * QKV_N + 8 * ks + c + 4] * qscale);
            qf[ks][3] = f2tf(Qp[(size_t)(r + 8) * QKV_N + 8 * ks + c + 4] * qscale);
        }
    }

    const int srow = tid >> 2;
    const int sc0  = (tid & 3) * 16;
    const float* kbase = g_qkv + (size_t)(b * SEQ) * QKV_N + HIDDEN + h * HEAD_DIM + sc0;

    auto load_chunk = [&](int ct, int buf) {
        const float* kp = kbase + (size_t)(ct * 64 + srow) * QKV_N;
        const float* vp = kp + HIDDEN;
        const uint32_t kd = smem_u32(&Kb[buf * KBUF + srow * KROW + sc0]);
        const uint32_t vd = smem_u32(&Vb[buf * VBUF + srow * VROW + sc0]);
#pragma unroll
        for (int i = 0; i < 4; i++) cp16(kd + i * 16, kp + i * 4);
#pragma unroll
        for (int i = 0; i < 4; i++) cp16(vd + i * 16, vp + i * 4);
    };

    float m0 = -INFINITY, m1 = -INFINITY, l0 = 0.f, l1 = 0.f;
    float o[8][4];
#pragma unroll
    for (int j = 0; j < 8; j++)
#pragma unroll
        for (int q = 0; q < 4; q++) o[j][q] = 0.f;

    // ldmatrix lane address offset within K buffer (bytes)
    const uint32_t kLane = (uint32_t)(lane & 15) * (KROW * 4) + (uint32_t)(lane & 16);

    load_chunk(0, 0);
    cp_commit();

    for (int ct = 0; ct < 16; ct++) {
        const int buf = ct & 1;
        cp_wait<0>();
        __syncthreads();
        if (ct + 1 < 16) load_chunk(ct + 1, buf ^ 1);
        cp_commit();

        const float* Vs = &Vb[buf * VBUF];
        const uint32_t Kbase = smem_u32(&Kb[buf * KBUF]) + kLane;

        // ---- S = Q @ K^T via ldsm4 K fragments ----
        float s[8][4];
#pragma unroll
        for (int j = 0; j < 8; j++)
#pragma unroll
            for (int q = 0; q < 4; q++) s[j][q] = 0.f;

#pragma unroll
        for (int ks = 0; ks < 8; ks++) {
#pragma unroll
            for (int j2 = 0; j2 < 4; j2++) {
                uint32_t kq[4];
                ldsm4(kq, Kbase + (uint32_t)j2 * (16 * KROW * 4) + ks * 32);
                mma8(s[2 * j2],     qf[ks][0], qf[ks][1], qf[ks][2], qf[ks][3], kq[0], kq[2]);
                mma8(s[2 * j2 + 1], qf[ks][0], qf[ks][1], qf[ks][2], qf[ks][3], kq[1], kq[3]);
            }
        }

        // ---- online softmax (base-2 domain) ----
        float mx0 = -INFINITY, mx1 = -INFINITY;
#pragma unroll
        for (int j = 0; j < 8; j++) {
            mx0 = fmaxf(mx0, fmaxf(s[j][0], s[j][1]));
            mx1 = fmaxf(mx1, fmaxf(s[j][2], s[j][3]));
        }
#pragma unroll
        for (int off = 1; off < 4; off <<= 1) {
            mx0 = fmaxf(mx0, __shfl_xor_sync(0xffffffffu, mx0, off));
            mx1 = fmaxf(mx1, __shfl_xor_sync(0xffffffffu, mx1, off));
        }
        const float nm0 = fmaxf(m0, mx0), nm1 = fmaxf(m1, mx1);
        const float cor0 = ex2(m0 - nm0), cor1 = ex2(m1 - nm1);
        m0 = nm0; m1 = nm1;
        float rs0 = 0.f, rs1 = 0.f;
#pragma unroll
        for (int j = 0; j < 8; j++) {
            s[j][0] = ex2(s[j][0] - nm0);
            s[j][1] = ex2(s[j][1] - nm0);
            s[j][2] = ex2(s[j][2] - nm1);
            s[j][3] = ex2(s[j][3] - nm1);
            rs0 += s[j][0] + s[j][1];
            rs1 += s[j][2] + s[j][3];
        }
#pragma unroll
        for (int off = 1; off < 4; off <<= 1) {
            rs0 += __shfl_xor_sync(0xffffffffu, rs0, off);
            rs1 += __shfl_xor_sync(0xffffffffu, rs1, off);
        }
        l0 = l0 * cor0 + rs0;
        l1 = l1 * cor1 + rs1;
#pragma unroll
        for (int j = 0; j < 8; j++) {
            o[j][0] *= cor0; o[j][1] *= cor0;
            o[j][2] *= cor1; o[j][3] *= cor1;
        }

        // ---- O += P @ V (D-frag -> A-frag via shuffles) ----
        const int sbase = lane & ~3;
        const int src1 = sbase | (c >> 1);
        const int src2 = sbase | 2 | (c >> 1);
        const bool odd = (c & 1);
#pragma unroll
        for (int kt = 0; kt < 8; kt++) {
            uint32_t p0 = f2tf(s[kt][0]), p1 = f2tf(s[kt][1]);
            uint32_t p2 = f2tf(s[kt][2]), p3 = f2tf(s[kt][3]);
            uint32_t x0 = __shfl_sync(0xffffffffu, p0, src1);
            uint32_t x1 = __shfl_sync(0xffffffffu, p1, src1);
            uint32_t x2 = __shfl_sync(0xffffffffu, p2, src1);
            uint32_t x3 = __shfl_sync(0xffffffffu, p3, src1);
            uint32_t y0 = __shfl_sync(0xffffffffu, p0, src2);
            uint32_t y1 = __shfl_sync(0xffffffffu, p1, src2);
            uint32_t y2 = __shfl_sync(0xffffffffu, p2, src2);
            uint32_t y3 = __shfl_sync(0xffffffffu, p3, src2);
            uint32_t a0 = odd ? x1 : x0;
            uint32_t a1 = odd ? x3 : x2;
            uint32_t a2 = odd ? y1 : y0;
            uint32_t a3 = odd ? y3 : y2;
#pragma unroll
            for (int j = 0; j < 8; j++) {
                uint32_t b0 = fbits(Vs[(8 * kt + c    ) * VROW + 8 * j + r]);
                uint32_t b1 = fbits(Vs[(8 * kt + c + 4) * VROW + 8 * j + r]);
                mma8(o[j], a0, a1, a2, a3, b0, b1);
            }
        }
    }

    const float inv0 = 1.f / l0, inv1 = 1.f / l1;
    const size_t gq = (size_t)(b * SEQ + qt * 128 + warp * 16);
#pragma unroll
    for (int j = 0; j < 8; j++) {
        const int col = h * HEAD_DIM + 8 * j + 2 * c;
        float2 v0, v1;
        v0.x = __uint_as_float(f2tf(o[j][0] * inv0));
        v0.y = __uint_as_float(f2tf(o[j][1] * inv0));
        v1.x = __uint_as_float(f2tf(o[j][2] * inv1));
        v1.y = __uint_as_float(f2tf(o[j][3] * inv1));
        *(float2*)&g_att[(gq + r) * HIDDEN + col]     = v0;
        *(float2*)&g_att[(gq + r + 8) * HIDDEN + col] = v1;
    }
}

// ---------------------------------------------------------------------------
extern "C" void kernel_launch(void* const* d_in, const int* in_sizes, int n_in,
                              void* d_out, int out_size) {
    const float* query = (const float*)d_in[0];
    const float* w_qkv = (const float*)d_in[1];
    const float* b_qkv = (const float*)d_in[2];
    const float* w_o   = (const float*)d_in[3];
    const float* b_o   = (const float*)d_in[4];
    float* out = (float*)d_out;

    float *gx, *gw1t, *gw2t, *gqkv, *gatt;
    cudaGetSymbolAddress((void**)&gx,   g_x);
    cudaGetSymbolAddress((void**)&gw1t, g_w1t);
    cudaGetSymbolAddress((void**)&gw2t, g_w2t);
    cudaGetSymbolAddress((void**)&gqkv, g_qkv);
    cudaGetSymbolAddress((void**)&gatt, g_att);

    cudaFuncSetAttribute(gemm_tc<QKV_N, true>,   cudaFuncAttributeMaxDynamicSharedMemorySize, GEMM_SMEM);
    cudaFuncSetAttribute(gemm_tc<HIDDEN, false>, cudaFuncAttributeMaxDynamicSharedMemorySize, GEMM_SMEM);
    cudaFuncSetAttribute(k_attention,            cudaFuncAttributeMaxDynamicSharedMemorySize, ATT_SMEM);

    // prep: round X; transpose+round weights
    {
        int n4x = MTOT * HIDDEN / 4;
        k_round<<<(n4x + 255) / 256, 256>>>(query, gx, n4x);
        dim3 tb(32, 8);
        k_transpose_tf<<<dim3(QKV_N / 32, HIDDEN / 32), tb>>>(w_qkv, gw1t, HIDDEN, QKV_N);
        k_transpose_tf<<<dim3(HIDDEN / 32, HIDDEN / 32), tb>>>(w_o, gw2t, HIDDEN, HIDDEN);
    }

    // QKV GEMM (rounds output to tf32 for attention)
    gemm_tc<QKV_N, true><<<dim3(QKV_N / 128, MTOT / 128), 256, GEMM_SMEM>>>(gx, gw1t, b_qkv, gqkv);

    // flash attention
    k_attention<<<dim3(SEQ / 128, HEADS, BATCH), 256, ATT_SMEM>>>();

    // output GEMM
    gemm_tc<HIDDEN, false><<<dim3(HIDDEN / 128, MTOT / 128), 256, GEMM_SMEM>>>(gatt, gw2t, b_o, out);
}